// round 15
// baseline (speedup 1.0000x reference)
#include <cuda_runtime.h>

// Problem: B=8, S=2048, D=256, H=8
//   q = p[:,1:,:], k = p[:,:-1,:]
//   scores = clip(q.k / 16, -10, 10), causal mask, softmax
//   y = attn @ e;  y *= 1/(i+1)
//   out = tile(y, 8) @ W_o^T  ==  y @ W_sum^T,  W_sum[d',d] = sum_h W_o[d', h*256+d]
//
// Clip(-10,10) before masking => exp bounded, no online-softmax needed.
//
// Scheduling: causal triangle paired — CTA handles q-tiles {i, 31-i} for
// exactly 33 tile-steps each; 128 CTAs = one perfectly balanced wave.

#define QS_STRIDE 260   // 64-row Q tile, padded stride (spreads rows across banks)

__device__ float g_Y[8 * 2048 * 256];     // attention output scratch (67 MB)
__device__ float g_Wsum[256 * 256];       // collapsed projection matrix

// ---------------------------------------------------------------------------
// Kernel 1: collapse W_o (256 x 2048) over the 8 head-copies -> W_sum (256 x 256)
// ---------------------------------------------------------------------------
__global__ void wsum_kernel(const float* __restrict__ Wo) {
    int idx = blockIdx.x * 256 + threadIdx.x;   // 65536 outputs
    int dp = idx >> 8;
    int d  = idx & 255;
    float s = 0.f;
#pragma unroll
    for (int h = 0; h < 8; h++) s += Wo[dp * 2048 + h * 256 + d];
    g_Wsum[idx] = s;
}

// ---------------------------------------------------------------------------
// Kernel 2: causal attention, fp32, tiled. One CTA per (batch, q-tile PAIR).
// Smem: Qs[64][260], KsT[256][64] (d-major), Es[64][256], Ws[64][64], denS[64]
// = 214272 bytes dynamic smem, 1 CTA/SM, 256 threads.
// GEMM1 micro-tile 4q x 4k; GEMM2 4q x 16d. FFMA-issue-bound by design.
// ---------------------------------------------------------------------------
__global__ __launch_bounds__(256, 1)
void attn_kernel(const float* __restrict__ e, const float* __restrict__ p) {
    extern __shared__ float sm[];
    float* Qs   = sm;                        // 64 * 260
    float* KsT  = Qs + 64 * QS_STRIDE;       // 256 * 64  (transposed: [d][k])
    float* Es   = KsT + 256 * 64;            // 64 * 256
    float* Ws   = Es + 64 * 256;             // 64 * 64   ([k][q])
    float* denS = Ws + 64 * 64;              // 64

    const int tid  = threadIdx.x;
    const int blk  = blockIdx.x;             // 0..127
    const int pair = blk >> 3;               // 0..15
    const int b    = blk & 7;

    const float* pb = p + (size_t)b * 2049 * 256;
    const float* eb = e + (size_t)b * 2048 * 256;

    // GEMM1 mapping: 4x2 warp grid; per-thread 4q x 4k micro-tile
    const int warp = tid >> 5, lane = tid & 31;
    const int q0 = (warp & 3) * 16 + (lane & 3) * 4;
    const int k0 = (warp >> 2) * 32 + (lane >> 2) * 4;

    // GEMM2 mapping: thread owns 4 q-rows x 16 d-cols
    const int qg2 = tid & 15, dg = tid >> 4;
    const int q0b = qg2 * 4, d0 = dg * 16;

    const float scale = 0.0625f;  // 1/sqrt(256)

#pragma unroll 1
    for (int sub = 0; sub < 2; sub++) {
        const int qt = sub == 0 ? (31 - pair) : pair;   // heavy tile first

        // ---- load Q tile (rows p[b][1 + qt*64 + r]) ----
#pragma unroll
        for (int it = 0; it < 16; it++) {
            int idx = tid + it * 256;
            int r = idx >> 6, c4 = idx & 63;
            float4 v = *(const float4*)(pb + (size_t)(1 + qt * 64 + r) * 256 + c4 * 4);
            *(float4*)(Qs + r * QS_STRIDE + c4 * 4) = v;
        }

        float acc[4][16];
#pragma unroll
        for (int i = 0; i < 4; i++)
#pragma unroll
            for (int c = 0; c < 16; c++) acc[i][c] = 0.f;
        float denacc[4] = {0.f, 0.f, 0.f, 0.f};

        for (int kt = 0; kt <= qt; kt++) {
            __syncthreads();   // prior consumers of KsT/Es/Ws done; Qs store visible

            // ---- load K tile transposed: KsT[d][k] ----
#pragma unroll
            for (int it = 0; it < 16; it++) {
                int idx = tid + it * 256;
                int r = idx & 63, c4 = idx >> 6;
                float4 v = *(const float4*)(pb + (size_t)(kt * 64 + r) * 256 + c4 * 4);
                KsT[(c4 * 4 + 0) * 64 + r] = v.x;
                KsT[(c4 * 4 + 1) * 64 + r] = v.y;
                KsT[(c4 * 4 + 2) * 64 + r] = v.z;
                KsT[(c4 * 4 + 3) * 64 + r] = v.w;
            }
            // ---- load E tile row-major ----
#pragma unroll
            for (int it = 0; it < 16; it++) {
                int idx = tid + it * 256;
                int r = idx >> 6, c4 = idx & 63;
                *(float4*)(Es + r * 256 + c4 * 4) =
                    *(const float4*)(eb + (size_t)(kt * 64 + r) * 256 + c4 * 4);
            }
            __syncthreads();

            // ---- GEMM1: S[4][4] = Q(4 x 256) . K(4 x 256)^T ----
            float s[4][4];
#pragma unroll
            for (int i = 0; i < 4; i++)
#pragma unroll
                for (int j = 0; j < 4; j++) s[i][j] = 0.f;

#pragma unroll 4
            for (int d4 = 0; d4 < 64; d4++) {
                float qv[4][4];
#pragma unroll
                for (int i = 0; i < 4; i++) {
                    float4 t = *(const float4*)(Qs + (q0 + i) * QS_STRIDE + d4 * 4);
                    qv[i][0] = t.x; qv[i][1] = t.y; qv[i][2] = t.z; qv[i][3] = t.w;
                }
#pragma unroll
                for (int u = 0; u < 4; u++) {
                    float4 t = *(const float4*)(KsT + (d4 * 4 + u) * 64 + k0);
                    float kf0 = t.x, kf1 = t.y, kf2 = t.z, kf3 = t.w;
#pragma unroll
                    for (int i = 0; i < 4; i++) {
                        s[i][0] += qv[i][u] * kf0;
                        s[i][1] += qv[i][u] * kf1;
                        s[i][2] += qv[i][u] * kf2;
                        s[i][3] += qv[i][u] * kf3;
                    }
                }
            }

            // ---- scale, clip, (mask only on diagonal tile), exp -> Ws[k][q] ----
            if (kt == qt) {
#pragma unroll
                for (int i = 0; i < 4; i++) {
                    int qloc = q0 + i;
#pragma unroll
                    for (int j = 0; j < 4; j++) {
                        int kloc = k0 + j;
                        float v = fminf(fmaxf(s[i][j] * scale, -10.f), 10.f);
                        float w = (kloc <= qloc) ? __expf(v) : 0.f;
                        Ws[kloc * 64 + qloc] = w;
                    }
                }
            } else {
#pragma unroll
                for (int i = 0; i < 4; i++) {
#pragma unroll
                    for (int j = 0; j < 4; j++) {
                        float v = fminf(fmaxf(s[i][j] * scale, -10.f), 10.f);
                        Ws[(k0 + j) * 64 + (q0 + i)] = __expf(v);
                    }
                }
            }
            __syncthreads();

            // ---- GEMM2: acc += W(64q x 64k) . E(64k x 256d), den += row-sums ----
#pragma unroll 2
            for (int kk = 0; kk < 64; kk++) {
                float4 wv = *(const float4*)(Ws + kk * 64 + q0b);
                float w0 = wv.x, w1 = wv.y, w2 = wv.z, w3 = wv.w;
                if (dg == 0) {
                    denacc[0] += w0; denacc[1] += w1; denacc[2] += w2; denacc[3] += w3;
                }
                float ev[16];
#pragma unroll
                for (int c = 0; c < 4; c++) {
                    float4 t = *(const float4*)(Es + kk * 256 + d0 + c * 4);
                    ev[c * 4 + 0] = t.x; ev[c * 4 + 1] = t.y;
                    ev[c * 4 + 2] = t.z; ev[c * 4 + 3] = t.w;
                }
#pragma unroll
                for (int c = 0; c < 16; c++) {
                    acc[0][c] += w0 * ev[c];
                    acc[1][c] += w1 * ev[c];
                    acc[2][c] += w2 * ev[c];
                    acc[3][c] += w3 * ev[c];
                }
            }
        }

        // ---- epilogue: y = acc / den / (q+1) -> g_Y ----
        if (dg == 0) {
#pragma unroll
            for (int i = 0; i < 4; i++) denS[q0b + i] = denacc[i];
        }
        __syncthreads();
#pragma unroll
        for (int i = 0; i < 4; i++) {
            int qglob = qt * 64 + q0b + i;
            float inv = 1.0f / (denS[q0b + i] * (float)(qglob + 1));
            float* dst = g_Y + ((size_t)(b * 2048 + qglob)) * 256 + d0;
#pragma unroll
            for (int c = 0; c < 4; c++) {
                float4 o;
                o.x = acc[i][c * 4 + 0] * inv;
                o.y = acc[i][c * 4 + 1] * inv;
                o.z = acc[i][c * 4 + 2] * inv;
                o.w = acc[i][c * 4 + 3] * inv;
                *(float4*)(dst + c * 4) = o;
            }
        }
        __syncthreads();   // denS/epilogue reads done before next subtile reuses smem
    }
}

// ---------------------------------------------------------------------------
// Kernel 3: out (16384 x 256) = g_Y (16384 x 256) @ g_Wsum^T (256 x 256)
// Block tile 64m x 64n, K looped in 64-chunks.
// ---------------------------------------------------------------------------
__global__ __launch_bounds__(256)
void proj_kernel(float* __restrict__ out) {
    __shared__ float Ys[64 * 68];   // [m][k], padded
    __shared__ float WT[64 * 64];   // [k][n], transposed on load

    const int tid = threadIdx.x;
    const int mblk = blockIdx.x * 64;
    const int nblk = blockIdx.y * 64;
    const int warp = tid >> 5, lane = tid & 31;
    const int m0 = (warp & 3) * 16 + (lane & 3) * 4;
    const int n0 = (warp >> 2) * 32 + (lane >> 2) * 4;

    float acc[4][4];
#pragma unroll
    for (int i = 0; i < 4; i++)
#pragma unroll
        for (int j = 0; j < 4; j++) acc[i][j] = 0.f;

    for (int kc = 0; kc < 256; kc += 64) {
        __syncthreads();
#pragma unroll
        for (int it = 0; it < 4; it++) {
            int idx = tid + it * 256;
            int r = idx >> 4, c4 = idx & 15;
            *(float4*)(Ys + r * 68 + c4 * 4) =
                *(const float4*)(g_Y + (size_t)(mblk + r) * 256 + kc + c4 * 4);
        }
#pragma unroll
        for (int it = 0; it < 4; it++) {
            int idx = tid + it * 256;
            int r = idx & 63, c4 = idx >> 6;
            float4 v = *(const float4*)(g_Wsum + (size_t)(nblk + r) * 256 + kc + c4 * 4);
            WT[(c4 * 4 + 0) * 64 + r] = v.x;
            WT[(c4 * 4 + 1) * 64 + r] = v.y;
            WT[(c4 * 4 + 2) * 64 + r] = v.z;
            WT[(c4 * 4 + 3) * 64 + r] = v.w;
        }
        __syncthreads();

#pragma unroll 4
        for (int k4 = 0; k4 < 16; k4++) {
            float yv[4][4];
#pragma unroll
            for (int i = 0; i < 4; i++) {
                float4 t = *(const float4*)(Ys + (m0 + i) * 68 + k4 * 4);
                yv[i][0] = t.x; yv[i][1] = t.y; yv[i][2] = t.z; yv[i][3] = t.w;
            }
#pragma unroll
            for (int u = 0; u < 4; u++) {
                float4 t = *(const float4*)(WT + (k4 * 4 + u) * 64 + n0);
#pragma unroll
                for (int i = 0; i < 4; i++) {
                    acc[i][0] += yv[i][u] * t.x;
                    acc[i][1] += yv[i][u] * t.y;
                    acc[i][2] += yv[i][u] * t.z;
                    acc[i][3] += yv[i][u] * t.w;
                }
            }
        }
    }

#pragma unroll
    for (int i = 0; i < 4; i++) {
        float4 o;
        o.x = acc[i][0]; o.y = acc[i][1]; o.z = acc[i][2]; o.w = acc[i][3];
        *(float4*)(out + (size_t)(mblk + m0 + i) * 256 + nblk + n0) = o;
    }
}

// ---------------------------------------------------------------------------
extern "C" void kernel_launch(void* const* d_in, const int* in_sizes, int n_in,
                              void* d_out, int out_size) {
    const float* e  = (const float*)d_in[0];   // (8, 2048, 256)
    const float* p  = (const float*)d_in[1];   // (8, 2049, 256)
    const float* Wo = (const float*)d_in[2];   // (256, 2048)
    float* out = (float*)d_out;                // (8, 2048, 256)

    const int attn_smem = (64 * QS_STRIDE + 256 * 64 + 64 * 256 + 64 * 64 + 64) * 4;
    cudaFuncSetAttribute(attn_kernel, cudaFuncAttributeMaxDynamicSharedMemorySize,
                         attn_smem);

    wsum_kernel<<<256, 256>>>(Wo);
    attn_kernel<<<128, 256, attn_smem>>>(e, p);
    proj_kernel<<<dim3(256, 4), 256>>>(out);
}

// round 17
// speedup vs baseline: 2.4962x; 2.4962x over previous
#include <cuda_runtime.h>

// B=8, S=2048, D=256, H=8.  Same validated skeleton as the 836us fp32 kernel
// (128 paired CTAs, 64x64 tiles), with both GEMMs moved to tensor cores via
// split-bf16 (hi+lo) m16n8k16 MMA: x ~= hi + lo, product = hh + hl + lh,
// dropped ll term ~2^-18 relative  ->  rel_err ~1e-5 << 1e-3.

__device__ float g_Y[8 * 2048 * 256];
__device__ float g_Wsum[256 * 256];

// smem layout (u32 word offsets). Strides chosen for conflict-free frag LDS:
//   Q/K: [64][132] u32 (bf16 pairs along d), 132 % 32 == 4 -> banks 4g+tg distinct
//   E:   [64][132] u32 == bf16[64][264] row-major (u16-indexed for B frags)
//   W:   [64][36]  u32 (bf16 pairs along k), 36 % 32 == 4
#define OQH 0
#define OQL 8448
#define OKH 16896
#define OKL 25344
#define OEH 33792
#define OEL 42240
#define OWH 50688
#define OWL 52992
#define ODEN 55296
#define SMEM_BYTES (55360 * 4)   // 221440 B

// ---------------------------------------------------------------------------
__global__ void wsum_kernel(const float* __restrict__ Wo) {
    int idx = blockIdx.x * 256 + threadIdx.x;
    int dp = idx >> 8, d = idx & 255;
    float s = 0.f;
#pragma unroll
    for (int h = 0; h < 8; h++) s += Wo[dp * 2048 + h * 256 + d];
    g_Wsum[idx] = s;
}

// ---------------------------------------------------------------------------
__device__ __forceinline__ void mma16816(float* c, const unsigned* a, const unsigned* b) {
    asm volatile(
        "mma.sync.aligned.m16n8k16.row.col.f32.bf16.bf16.f32 "
        "{%0,%1,%2,%3}, {%4,%5,%6,%7}, {%8,%9}, {%0,%1,%2,%3};\n"
        : "+f"(c[0]), "+f"(c[1]), "+f"(c[2]), "+f"(c[3])
        : "r"(a[0]), "r"(a[1]), "r"(a[2]), "r"(a[3]), "r"(b[0]), "r"(b[1]));
}

// split x0,x1 into bf16 hi-pair (packed u32, x0 in low 16) and lo-pair
__device__ __forceinline__ void split2(float x0, float x1, unsigned& hi, unsigned& lo) {
    unsigned u0 = __float_as_uint(x0), u1 = __float_as_uint(x1);
    unsigned r0 = (u0 + 0x7FFFu + ((u0 >> 16) & 1u)) & 0xFFFF0000u;  // bf16_rn bits<<16
    unsigned r1 = (u1 + 0x7FFFu + ((u1 >> 16) & 1u)) & 0xFFFF0000u;
    hi = r1 | (r0 >> 16);
    float l0 = x0 - __uint_as_float(r0);
    float l1 = x1 - __uint_as_float(r1);
    asm("cvt.rn.bf16x2.f32 %0, %1, %2;" : "=r"(lo) : "f"(l1), "f"(l0));  // l0 -> low16
}

// ---------------------------------------------------------------------------
__global__ __launch_bounds__(256, 1)
void attn_kernel(const float* __restrict__ e, const float* __restrict__ p) {
    extern __shared__ unsigned smu[];
    float* sDen = (float*)(smu + ODEN);
    const unsigned short* sEh16 = (const unsigned short*)(smu + OEH);
    const unsigned short* sEl16 = (const unsigned short*)(smu + OEL);

    const int tid = threadIdx.x;
    const int lane = tid & 31, warp = tid >> 5;
    const int g = lane >> 2, tg = lane & 3;        // mma group / thread-in-group
    const int mw = (warp & 3) * 16;                // q strip
    const int nw = (warp >> 2) * 32;               // key strip (GEMM1)
    const int dw = (warp >> 2) * 128;              // d strip (GEMM2)
    const int blk = blockIdx.x, pr = blk >> 3, b = blk & 7;

    const float* pb = p + (size_t)b * 2049 * 256;
    const float* eb = e + (size_t)b * 2048 * 256;
    const float scale = 0.0625f;

#pragma unroll 1
    for (int sub = 0; sub < 2; sub++) {
        const int qt = sub ? pr : 31 - pr;

        if (tid < 64) sDen[tid] = 0.f;

        // ---- convert Q tile -> hi/lo bf16 pairs ----
#pragma unroll
        for (int it = 0; it < 16; it++) {
            int t = tid + it * 256, row = t >> 6, quad = t & 63;
            float4 v = *(const float4*)(pb + (size_t)(1 + qt * 64 + row) * 256 + quad * 4);
            unsigned h01, l01, h23, l23;
            split2(v.x, v.y, h01, l01); split2(v.z, v.w, h23, l23);
            *(uint2*)&smu[OQH + row * 132 + quad * 2] = make_uint2(h01, h23);
            *(uint2*)&smu[OQL + row * 132 + quad * 2] = make_uint2(l01, l23);
        }

        float acc[16][4];
#pragma unroll
        for (int i = 0; i < 16; i++)
#pragma unroll
            for (int j = 0; j < 4; j++) acc[i][j] = 0.f;
        float den0 = 0.f, den1 = 0.f;

        for (int kt = 0; kt <= qt; kt++) {
            __syncthreads();   // prior consumers done; Q/den writes visible later

            // ---- convert K and E tiles ----
#pragma unroll
            for (int it = 0; it < 16; it++) {
                int t = tid + it * 256, row = t >> 6, quad = t & 63;
                float4 v = *(const float4*)(pb + (size_t)(kt * 64 + row) * 256 + quad * 4);
                unsigned h01, l01, h23, l23;
                split2(v.x, v.y, h01, l01); split2(v.z, v.w, h23, l23);
                *(uint2*)&smu[OKH + row * 132 + quad * 2] = make_uint2(h01, h23);
                *(uint2*)&smu[OKL + row * 132 + quad * 2] = make_uint2(l01, l23);
                float4 w = *(const float4*)(eb + (size_t)(kt * 64 + row) * 256 + quad * 4);
                split2(w.x, w.y, h01, l01); split2(w.z, w.w, h23, l23);
                *(uint2*)&smu[OEH + row * 132 + quad * 2] = make_uint2(h01, h23);
                *(uint2*)&smu[OEL + row * 132 + quad * 2] = make_uint2(l01, l23);
            }
            __syncthreads();

            // ---- GEMM1: S(64x64) = Q . K^T via 3-term split MMA ----
            float sf[4][4];
#pragma unroll
            for (int i = 0; i < 4; i++)
#pragma unroll
                for (int j = 0; j < 4; j++) sf[i][j] = 0.f;

#pragma unroll
            for (int ks = 0; ks < 16; ks++) {
                int kw = ks * 8 + tg;
                int ra = (mw + g) * 132 + kw, rb = (mw + g + 8) * 132 + kw;
                unsigned ah[4] = {smu[OQH + ra], smu[OQH + rb], smu[OQH + ra + 4], smu[OQH + rb + 4]};
                unsigned al[4] = {smu[OQL + ra], smu[OQL + rb], smu[OQL + ra + 4], smu[OQL + rb + 4]};
#pragma unroll
                for (int nt = 0; nt < 4; nt++) {
                    int rk = (nw + nt * 8 + g) * 132 + kw;
                    unsigned bh[2] = {smu[OKH + rk], smu[OKH + rk + 4]};
                    unsigned bl[2] = {smu[OKL + rk], smu[OKL + rk + 4]};
                    mma16816(sf[nt], ah, bh);
                    mma16816(sf[nt], ah, bl);
                    mma16816(sf[nt], al, bh);
                }
            }

            // ---- softmax weights -> W (hi/lo), den accumulate ----
            const bool diag = (kt == qt);
#pragma unroll
            for (int nt = 0; nt < 4; nt++) {
                int kb = nw + nt * 8 + tg * 2;
                float v0 = fminf(fmaxf(sf[nt][0] * scale, -10.f), 10.f);
                float v1 = fminf(fmaxf(sf[nt][1] * scale, -10.f), 10.f);
                float v2 = fminf(fmaxf(sf[nt][2] * scale, -10.f), 10.f);
                float v3 = fminf(fmaxf(sf[nt][3] * scale, -10.f), 10.f);
                float w0 = __expf(v0), w1 = __expf(v1), w2 = __expf(v2), w3 = __expf(v3);
                if (diag) {
                    int q0r = mw + g, q1r = mw + g + 8;
                    if (kb > q0r)     w0 = 0.f;
                    if (kb + 1 > q0r) w1 = 0.f;
                    if (kb > q1r)     w2 = 0.f;
                    if (kb + 1 > q1r) w3 = 0.f;
                }
                den0 += w0 + w1; den1 += w2 + w3;
                unsigned h, l;
                int wc = (nw >> 1) + nt * 4 + tg;
                split2(w0, w1, h, l);
                smu[OWH + (mw + g) * 36 + wc] = h;  smu[OWL + (mw + g) * 36 + wc] = l;
                split2(w2, w3, h, l);
                smu[OWH + (mw + g + 8) * 36 + wc] = h;  smu[OWL + (mw + g + 8) * 36 + wc] = l;
            }
            __syncthreads();

            // ---- GEMM2: Y(64x256) += W . E via 3-term split MMA ----
#pragma unroll
            for (int ks2 = 0; ks2 < 4; ks2++) {
                int kw = ks2 * 8 + tg;
                int ra = (mw + g) * 36 + kw, rb = (mw + g + 8) * 36 + kw;
                unsigned wh[4] = {smu[OWH + ra], smu[OWH + rb], smu[OWH + ra + 4], smu[OWH + rb + 4]};
                unsigned wl[4] = {smu[OWL + ra], smu[OWL + rb], smu[OWL + ra + 4], smu[OWL + rb + 4]};
                int k0a = ks2 * 16 + tg * 2;
#pragma unroll
                for (int dt = 0; dt < 16; dt++) {
                    int d = dw + dt * 8 + g;
                    unsigned bh[2], bl[2];
                    bh[0] = (unsigned)sEh16[k0a * 264 + d]       | ((unsigned)sEh16[(k0a + 1) * 264 + d] << 16);
                    bh[1] = (unsigned)sEh16[(k0a + 8) * 264 + d] | ((unsigned)sEh16[(k0a + 9) * 264 + d] << 16);
                    bl[0] = (unsigned)sEl16[k0a * 264 + d]       | ((unsigned)sEl16[(k0a + 1) * 264 + d] << 16);
                    bl[1] = (unsigned)sEl16[(k0a + 8) * 264 + d] | ((unsigned)sEl16[(k0a + 9) * 264 + d] << 16);
                    mma16816(acc[dt], wh, bh);
                    mma16816(acc[dt], wh, bl);
                    mma16816(acc[dt], wl, bh);
                }
            }
        }

        // ---- epilogue: reduce den, scale, store y ----
        float r0 = den0 + __shfl_xor_sync(0xffffffffu, den0, 1);
        r0 += __shfl_xor_sync(0xffffffffu, r0, 2);
        float r1 = den1 + __shfl_xor_sync(0xffffffffu, den1, 1);
        r1 += __shfl_xor_sync(0xffffffffu, r1, 2);
        if (tg == 0) {
            atomicAdd(&sDen[mw + g], r0);
            atomicAdd(&sDen[mw + g + 8], r1);
        }
        __syncthreads();
        int q0g = qt * 64 + mw + g, q1g = q0g + 8;
        float inv0 = 1.f / (sDen[mw + g] * (float)(q0g + 1));
        float inv1 = 1.f / (sDen[mw + g + 8] * (float)(q1g + 1));
#pragma unroll
        for (int dt = 0; dt < 16; dt++) {
            int d = dw + dt * 8 + tg * 2;
            float2 o0 = make_float2(acc[dt][0] * inv0, acc[dt][1] * inv0);
            float2 o1 = make_float2(acc[dt][2] * inv1, acc[dt][3] * inv1);
            *(float2*)(g_Y + ((size_t)(b * 2048 + q0g)) * 256 + d) = o0;
            *(float2*)(g_Y + ((size_t)(b * 2048 + q1g)) * 256 + d) = o1;
        }
        __syncthreads();   // den reads done before next sub zeroes
    }
}

// ---------------------------------------------------------------------------
// proj: out (16384 x 256) = g_Y @ g_Wsum^T   (unchanged fp32, audited)
__global__ __launch_bounds__(256)
void proj_kernel(float* __restrict__ out) {
    __shared__ float Ys[64 * 68];
    __shared__ float WT[64 * 64];

    const int tid = threadIdx.x;
    const int mblk = blockIdx.x * 64;
    const int nblk = blockIdx.y * 64;
    const int warp = tid >> 5, lane = tid & 31;
    const int m0 = (warp & 3) * 16 + (lane & 3) * 4;
    const int n0 = (warp >> 2) * 32 + (lane >> 2) * 4;

    float acc[4][4];
#pragma unroll
    for (int i = 0; i < 4; i++)
#pragma unroll
        for (int j = 0; j < 4; j++) acc[i][j] = 0.f;

    for (int kc = 0; kc < 256; kc += 64) {
        __syncthreads();
#pragma unroll
        for (int it = 0; it < 4; it++) {
            int idx = tid + it * 256;
            int r = idx >> 4, c4 = idx & 15;
            *(float4*)(Ys + r * 68 + c4 * 4) =
                *(const float4*)(g_Y + (size_t)(mblk + r) * 256 + kc + c4 * 4);
        }
#pragma unroll
        for (int it = 0; it < 4; it++) {
            int idx = tid + it * 256;
            int r = idx & 63, c4 = idx >> 6;
            float4 v = *(const float4*)(g_Wsum + (size_t)(nblk + r) * 256 + kc + c4 * 4);
            WT[(c4 * 4 + 0) * 64 + r] = v.x;
            WT[(c4 * 4 + 1) * 64 + r] = v.y;
            WT[(c4 * 4 + 2) * 64 + r] = v.z;
            WT[(c4 * 4 + 3) * 64 + r] = v.w;
        }
        __syncthreads();

#pragma unroll 4
        for (int k4 = 0; k4 < 16; k4++) {
            float yv[4][4];
#pragma unroll
            for (int i = 0; i < 4; i++) {
                float4 t = *(const float4*)(Ys + (m0 + i) * 68 + k4 * 4);
                yv[i][0] = t.x; yv[i][1] = t.y; yv[i][2] = t.z; yv[i][3] = t.w;
            }
#pragma unroll
            for (int u = 0; u < 4; u++) {
                float4 t = *(const float4*)(WT + (k4 * 4 + u) * 64 + n0);
#pragma unroll
                for (int i = 0; i < 4; i++) {
                    acc[i][0] += yv[i][u] * t.x;
                    acc[i][1] += yv[i][u] * t.y;
                    acc[i][2] += yv[i][u] * t.z;
                    acc[i][3] += yv[i][u] * t.w;
                }
            }
        }
    }

#pragma unroll
    for (int i = 0; i < 4; i++) {
        float4 o;
        o.x = acc[i][0]; o.y = acc[i][1]; o.z = acc[i][2]; o.w = acc[i][3];
        *(float4*)(out + (size_t)(mblk + m0 + i) * 256 + nblk + n0) = o;
    }
}

// ---------------------------------------------------------------------------
extern "C" void kernel_launch(void* const* d_in, const int* in_sizes, int n_in,
                              void* d_out, int out_size) {
    const float* e  = (const float*)d_in[0];
    const float* p  = (const float*)d_in[1];
    const float* Wo = (const float*)d_in[2];
    float* out = (float*)d_out;

    cudaFuncSetAttribute(attn_kernel, cudaFuncAttributeMaxDynamicSharedMemorySize,
                         SMEM_BYTES);

    wsum_kernel<<<256, 256>>>(Wo);
    attn_kernel<<<128, 256, SMEM_BYTES>>>(e, p);
    proj_kernel<<<dim3(256, 4), 256>>>(out);
}